// round 6
// baseline (speedup 1.0000x reference)
#include <cuda_runtime.h>
#include <cuda_bf16.h>
#include <cstdint>

// OverlapPatchEmbed: x (B=64, C=3, H=224, W=224) f32 -> out (B, 729, C, 256) f32
// out[b][pi*27+pj][c][r*16+s] = x[b][c][pi*8+r][pj*8+s]
//
// Block = (b, c, pi). Load the contiguous 16-row band with coalesced LDG.128,
// scatter each float4 into patch-major smem (1-2 STS per load: the pj overlap
// duplication happens here). Then 27 threads each issue one 1KB
// cp.async.bulk smem->gmem store (TMA path): no LDS, no STG, async drain.

namespace {
constexpr int B  = 64;
constexpr int C  = 3;
constexpr int H  = 224;
constexpr int W  = 224;       // 56 float4 per input row
constexpr int N  = 27;
constexpr int TPB = 256;

constexpr int W4      = W / 4;        // 56
constexpr int ROWS    = 16;
constexpr int LOAD_V  = ROWS * W4;    // 896 float4 per band
constexpr int PSTRIDE = 66;           // float4 stride per patch slot (1056B) - conflict-free
constexpr int NBLOCKS = B * C * N;    // 5184
constexpr int LK = 4;                 // ceil(896/256)
}

__global__ __launch_bounds__(TPB)
void overlap_patch_kernel(const float4* __restrict__ x, float4* __restrict__ out)
{
    __shared__ alignas(16) float4 s[N * PSTRIDE];   // 27*66*16 = 28512 B

    const int bx  = blockIdx.x;
    const int pi  = bx % N;
    const int c   = (bx / N) % C;
    const int b   = bx / (N * C);
    const int tid = threadIdx.x;

    // ---- load band + scatter into patch-major smem ----
    const int in_base = ((b * C + c) * H + pi * 8) * W4;

    float4 lv[LK];
    int    li[LK];
    #pragma unroll
    for (int k = 0; k < LK; k++) {
        int i = tid + k * TPB;
        li[k] = i;
        if (i < LOAD_V) lv[k] = __ldg(&x[in_base + i]);
    }

    #pragma unroll
    for (int k = 0; k < LK; k++) {
        int i = li[k];
        if (i < LOAD_V) {
            int row = i / W4;
            int c4  = i - row * W4;          // float4 column 0..55
            int r4  = row * 4;
            int pj0 = c4 >> 1;               // copy 1: s4 = c4&1
            if (pj0 < N)
                s[pj0 * PSTRIDE + r4 + (c4 & 1)] = lv[k];
            int pj1 = pj0 - 1;               // copy 2: s4 = (c4&1)+2
            if (pj1 >= 0)
                s[pj1 * PSTRIDE + r4 + (c4 & 1) + 2] = lv[k];
        }
    }

    // make smem writes visible to the async (TMA) proxy, then barrier
    asm volatile("fence.proxy.async.shared::cta;" ::: "memory");
    __syncthreads();

    // ---- async bulk store: one 1KB patch per thread (tid < 27) ----
    const long long ob0 = ((long long)(b * (N * N) + pi * N) * C + c) * 64;
    if (tid < N) {
        uint32_t src;
        asm("{ .reg .u64 t; cvta.to.shared.u64 t, %1; cvt.u32.u64 %0, t; }"
            : "=r"(src) : "l"(&s[tid * PSTRIDE]));
        const float4* dst = out + ob0 + (long long)tid * (C * 64);
        asm volatile(
            "cp.async.bulk.global.shared::cta.bulk_group [%0], [%1], %2;"
            :: "l"(dst), "r"(src), "n"(1024) : "memory");
        asm volatile("cp.async.bulk.commit_group;" ::: "memory");
        // wait only for smem reads; gmem writes drain asynchronously and are
        // guaranteed complete by kernel termination
        asm volatile("cp.async.bulk.wait_group.read 0;" ::: "memory");
    }
}

extern "C" void kernel_launch(void* const* d_in, const int* in_sizes, int n_in,
                              void* d_out, int out_size)
{
    const float4* x = (const float4*)d_in[0];
    float4* out = (float4*)d_out;
    overlap_patch_kernel<<<NBLOCKS, TPB>>>(x, out);
}

// round 7
// speedup vs baseline: 1.0420x; 1.0420x over previous
#include <cuda_runtime.h>
#include <cuda_bf16.h>
#include <cstdint>

// OverlapPatchEmbed: x (B=64, C=3, H=224, W=224) f32 -> out (B, 729, C, 256) f32
// out[b][pi*27+pj][c][r*16+s] = x[b][c][pi*8+r][pj*8+s]
//
// Persistent single-wave version of the R3 smem kernel:
//   grid = 864 blocks, each handling 6 consecutive (b,c,pi) tiles.
//   Next tile's 4 LDG.128s are issued into registers before the current
//   tile's store phase, hiding load latency under the LDS/STG work.
//   Consecutive tiles are adjacent pi-bands (8 of 16 rows shared -> L1/L2 hits).

namespace {
constexpr int B  = 64;
constexpr int C  = 3;
constexpr int H  = 224;
constexpr int W  = 224;     // 56 float4 per row
constexpr int N  = 27;
constexpr int TPB = 256;

constexpr int W4      = W / 4;        // 56
constexpr int ROWS    = 16;
constexpr int LOAD_V  = ROWS * W4;    // 896 float4 per tile
constexpr int PITCH4  = 60;           // 240-float pitch (mod 32 == 16): conflict-free
constexpr int STORE_V = N * 64;       // 1728 float4 per tile
constexpr int NTILES  = B * C * N;    // 5184
constexpr int TPB_TILES = 6;          // tiles per block
constexpr int NBLOCKS = NTILES / TPB_TILES;  // 864 -> single wave on 148 SMs

constexpr int LK = 4;                 // ceil(896/256)
constexpr int SK = 7;                 // ceil(1728/256)
}

__device__ __forceinline__ int tile_in_base(int t)
{
    int pi = t % N;
    int c  = (t / N) % C;
    int b  = t / (N * C);
    return ((b * C + c) * H + pi * 8) * W4;   // float4 index
}

__global__ __launch_bounds__(TPB, 6)
void overlap_patch_kernel(const float4* __restrict__ x, float4* __restrict__ out)
{
    __shared__ float4 s[ROWS * PITCH4];   // 15360 bytes

    const int tid = threadIdx.x;
    const int t0  = blockIdx.x * TPB_TILES;

    // prefetch tile t0 into registers
    float4 lv[LK];
    {
        const int base = tile_in_base(t0);
        #pragma unroll
        for (int k = 0; k < LK; k++) {
            int i = tid + k * TPB;
            if (i < LOAD_V) lv[k] = __ldg(&x[base + i]);
        }
    }

    #pragma unroll
    for (int it = 0; it < TPB_TILES; it++) {
        const int t = t0 + it;

        // STS current tile's band into padded smem
        #pragma unroll
        for (int k = 0; k < LK; k++) {
            int i = tid + k * TPB;
            if (i < LOAD_V) {
                int row = i / W4;
                int col = i - row * W4;
                s[row * PITCH4 + col] = lv[k];
            }
        }

        // issue next tile's loads (long-scoreboard wait lands after store phase)
        float4 nv[LK];
        if (it + 1 < TPB_TILES) {
            const int nbase = tile_in_base(t + 1);
            #pragma unroll
            for (int k = 0; k < LK; k++) {
                int i = tid + k * TPB;
                if (i < LOAD_V) nv[k] = __ldg(&x[nbase + i]);
            }
        }

        __syncthreads();   // band visible

        // store phase: smem -> fully coalesced STG.128
        {
            int pi = t % N;
            int c  = (t / N) % C;
            int b  = t / (N * C);
            const int ob0 = ((b * (N * N) + pi * N) * C + c) * 64;

            float4 sv[SK];
            #pragma unroll
            for (int k = 0; k < SK; k++) {
                int j = tid + k * TPB;
                if (j < STORE_V) {
                    int pj = j >> 6;
                    int q  = j & 63;
                    int r  = q >> 2;
                    int s4 = q & 3;
                    sv[k] = s[r * PITCH4 + pj * 2 + s4];
                }
            }
            #pragma unroll
            for (int k = 0; k < SK; k++) {
                int j = tid + k * TPB;
                if (j < STORE_V) {
                    int pj = j >> 6;
                    int q  = j & 63;
                    out[ob0 + pj * (C * 64) + q] = sv[k];
                }
            }
        }

        __syncthreads();   // smem reads done before next STS

        #pragma unroll
        for (int k = 0; k < LK; k++) lv[k] = nv[k];
    }
}

extern "C" void kernel_launch(void* const* d_in, const int* in_sizes, int n_in,
                              void* d_out, int out_size)
{
    const float4* x = (const float4*)d_in[0];
    float4* out = (float4*)d_out;
    overlap_patch_kernel<<<NBLOCKS, TPB>>>(x, out);
}

// round 8
// speedup vs baseline: 1.2219x; 1.1727x over previous
#include <cuda_runtime.h>
#include <cuda_bf16.h>
#include <cuda_pipeline.h>
#include <cstdint>

// OverlapPatchEmbed: x (B=64, C=3, H=224, W=224) f32 -> out (B, 729, C, 256) f32
// out[b][pi*27+pj][c][r*16+s] = x[b][c][pi*8+r][pj*8+s]
//
// R3 structure (block = (b,c,pi), smem-staged, 2 phases) with:
//  - load phase via cp.async (LDGSTS.128): no register round-trip, no
//    long-scoreboard stall on load data; single smem buffer keeps occupancy.
//  - store phase writes with __stcs (evict-first) so the 143MB output stream
//    doesn't evict the 38.5MB input from L2 (band re-reads stay L2-resident).

namespace {
constexpr int B  = 64;
constexpr int C  = 3;
constexpr int H  = 224;
constexpr int W  = 224;   // 56 float4 per row
constexpr int N  = 27;
constexpr int TPB = 256;

constexpr int W4      = W / 4;          // 56 float4 per input row
constexpr int ROWS    = 16;
constexpr int LOAD_V  = ROWS * W4;      // 896 float4 per block
constexpr int PITCH4  = 60;             // 240-float pitch (mod 32 == 16): conflict-free
constexpr int STORE_V = N * 64;         // 1728 float4 per block
constexpr int NBLOCKS = B * C * N;      // 5184

constexpr int LK = 4;                   // ceil(896/256)
constexpr int SK = 7;                   // ceil(1728/256)
}

__global__ __launch_bounds__(TPB)
void overlap_patch_kernel(const float4* __restrict__ x, float4* __restrict__ out)
{
    __shared__ float4 s[ROWS * PITCH4];   // 15360 bytes

    const int bx  = blockIdx.x;
    const int pi  = bx % N;
    const int c   = (bx / N) % C;
    const int b   = bx / (N * C);
    const int tid = threadIdx.x;

    // ---- load phase: contiguous gmem band -> padded smem via LDGSTS ----
    const int in_base = ((b * C + c) * H + pi * 8) * W4;   // float4 index
    #pragma unroll
    for (int k = 0; k < LK; k++) {
        int i = tid + k * TPB;
        if (i < LOAD_V) {
            int row = i / W4;
            int col = i - row * W4;
            __pipeline_memcpy_async(&s[row * PITCH4 + col], &x[in_base + i], 16);
        }
    }
    __pipeline_commit();
    __pipeline_wait_prior(0);
    __syncthreads();

    // ---- store phase: smem -> coalesced streaming STG.128 ----
    const int ob0 = ((b * (N * N) + pi * N) * C + c) * 64;

    float4 sv[SK];
    #pragma unroll
    for (int k = 0; k < SK; k++) {
        int j = tid + k * TPB;
        if (j < STORE_V) {
            int pj = j >> 6;
            int q  = j & 63;
            int r  = q >> 2;
            int s4 = q & 3;
            sv[k] = s[r * PITCH4 + pj * 2 + s4];
        }
    }
    #pragma unroll
    for (int k = 0; k < SK; k++) {
        int j = tid + k * TPB;
        if (j < STORE_V) {
            int pj = j >> 6;
            int q  = j & 63;
            __stcs(&out[ob0 + pj * (C * 64) + q], sv[k]);
        }
    }
}

extern "C" void kernel_launch(void* const* d_in, const int* in_sizes, int n_in,
                              void* d_out, int out_size)
{
    const float4* x = (const float4*)d_in[0];
    float4* out = (float4*)d_out;
    overlap_patch_kernel<<<NBLOCKS, TPB>>>(x, out);
}

// round 9
// speedup vs baseline: 1.3359x; 1.0933x over previous
#include <cuda_runtime.h>
#include <cuda_bf16.h>
#include <cuda_pipeline.h>
#include <cstdint>

// OverlapPatchEmbed: x (B=64, C=3, H=224, W=224) f32 -> out (B, 729, C, 256) f32
// out[b][pi*27+pj][c][r*16+s] = x[b][c][pi*8+r][pj*8+s]
//
// Triple-band version: block = (b, c, g) with g in [0,9), covering
// pi = 3g..3g+2. Loads 32 contiguous rows ONCE (the three 16-row bands
// overlap by 8 rows each), eliminating the 2x read amplification of the
// per-band kernel. Load via cp.async (LDGSTS.128), store via streaming
// STG.128; smem pitch 60 float4 keeps all LDS.128 conflict-free.

namespace {
constexpr int B  = 64;
constexpr int C  = 3;
constexpr int H  = 224;
constexpr int W  = 224;      // 56 float4 per row
constexpr int N  = 27;
constexpr int G  = 9;        // pi groups of 3
constexpr int TPB = 256;

constexpr int W4      = W / 4;          // 56
constexpr int GROWS   = 32;             // rows per 3-band group (8*3 + 8)
constexpr int LOAD_V  = GROWS * W4;     // 1792 float4 per block (exactly 7*256)
constexpr int PITCH4  = 60;             // 240-float pitch (mod 32 == 16): conflict-free
constexpr int STORE_V = N * 64;         // 1728 float4 per band
constexpr int NBLOCKS = B * C * G;      // 1728

constexpr int LK = LOAD_V / TPB;        // 7, exact
constexpr int SK = 7;                   // ceil(1728/256)
}

__global__ __launch_bounds__(TPB, 7)
void overlap_patch_kernel(const float4* __restrict__ x, float4* __restrict__ out)
{
    __shared__ float4 s[GROWS * PITCH4];   // 30720 bytes

    const int bx  = blockIdx.x;
    const int g   = bx % G;
    const int c   = (bx / G) % C;
    const int b   = bx / (G * C);
    const int tid = threadIdx.x;
    const int pi0 = g * 3;

    // ---- load phase: 32 contiguous rows -> padded smem via LDGSTS ----
    const int in_base = ((b * C + c) * H + pi0 * 8) * W4;   // float4 index
    #pragma unroll
    for (int k = 0; k < LK; k++) {
        int i = tid + k * TPB;                 // 0..1791, no bounds check (exact)
        int row = i / W4;
        int col = i - row * W4;
        __pipeline_memcpy_async(&s[row * PITCH4 + col], &x[in_base + i], 16);
    }
    __pipeline_commit();
    __pipeline_wait_prior(0);
    __syncthreads();

    // ---- store phase: 3 bands, each fully coalesced streaming STG.128 ----
    #pragma unroll
    for (int sub = 0; sub < 3; sub++) {
        const int pi  = pi0 + sub;
        const int ob0 = ((b * (N * N) + pi * N) * C + c) * 64;
        const int srow0 = sub * 8;             // smem row offset of this band

        float4 sv[SK];
        #pragma unroll
        for (int k = 0; k < SK; k++) {
            int j = tid + k * TPB;
            if (j < STORE_V) {
                int pj = j >> 6;
                int q  = j & 63;
                int r  = q >> 2;
                int s4 = q & 3;
                sv[k] = s[(srow0 + r) * PITCH4 + pj * 2 + s4];
            }
        }
        #pragma unroll
        for (int k = 0; k < SK; k++) {
            int j = tid + k * TPB;
            if (j < STORE_V) {
                int pj = j >> 6;
                int q  = j & 63;
                __stcs(&out[ob0 + pj * (C * 64) + q], sv[k]);
            }
        }
    }
}

extern "C" void kernel_launch(void* const* d_in, const int* in_sizes, int n_in,
                              void* d_out, int out_size)
{
    const float4* x = (const float4*)d_in[0];
    float4* out = (float4*)d_out;
    overlap_patch_kernel<<<NBLOCKS, TPB>>>(x, out);
}